// round 1
// baseline (speedup 1.0000x reference)
#include <cuda_runtime.h>

// Problem constants (from reference): B=4096, D=512, K=10, L=256, V=80
#define BQ 4096
#define DD 512
#define KK 10
#define LL 256
#define VV 80

// Scratch for alpha[0:10], beta[10:20], kappa[20:30] per batch row.
__device__ float g_abk[BQ * 30];

// exp(e) for e in [-50, 0], FMA-pipe only (no MUFU).
// exp(e) = 2^(e*log2e) = 2^i * 2^f, i=floor(t), f in [0,1), deg-6 Taylor (err ~2e-6 rel).
__device__ __forceinline__ float fast_exp_neg(float e) {
    float t = e * 1.44269504088896341f;
    int i = __float2int_rd(t);            // t in [-72.14, 0] -> i in [-73, 0]
    float f = t - (float)i;
    float p = 1.5403530393381610e-4f;
    p = fmaf(p, f, 1.3333558146428443e-3f);
    p = fmaf(p, f, 9.6181291076284772e-3f);
    p = fmaf(p, f, 5.5504108664821580e-2f);
    p = fmaf(p, f, 2.4022650695910071e-1f);
    p = fmaf(p, f, 6.9314718055994531e-1f);
    p = fmaf(p, f, 1.0f);
    return p * __int_as_float((i + 127) << 23);
}

// Kernel A: raw = X@W + b, activations, write kappa to output + abk scratch.
// 128 blocks x 256 threads, each block does 32 batch rows.
// Warp layout: warp w owns rows 4w..4w+3, lane = output column (lanes 30,31 idle at write).
__global__ __launch_bounds__(256) void gemm_act_kernel(
    const float* __restrict__ X, const float* __restrict__ W,
    const float* __restrict__ bias, const float* __restrict__ prev_kappa,
    const float* __restrict__ kappa_scale_p, float* __restrict__ out_kappa)
{
    __shared__ float Xs[32][128];
    __shared__ float Wsh[128 * 30 + 32];   // +32 pad: lanes 30/31 read harmlessly
    const int tid  = threadIdx.x;
    const int warp = tid >> 5;
    const int lane = tid & 31;
    const int b0   = blockIdx.x * 32;

    float acc[4] = {0.f, 0.f, 0.f, 0.f};

    for (int dt = 0; dt < DD; dt += 128) {
        __syncthreads();
        // W slab [dt:dt+128, 0:30] is contiguous in row-major W.
        for (int i = tid; i < 128 * 30; i += 256) Wsh[i] = W[dt * 30 + i];
        for (int i = tid; i < 32 * 128; i += 256) {
            int r = i >> 7, c = i & 127;
            Xs[r][c] = X[(size_t)(b0 + r) * DD + dt + c];
        }
        __syncthreads();
        #pragma unroll 4
        for (int d = 0; d < 128; ++d) {
            float wv = Wsh[d * 30 + lane];
            acc[0] = fmaf(Xs[warp * 4 + 0][d], wv, acc[0]);
            acc[1] = fmaf(Xs[warp * 4 + 1][d], wv, acc[1]);
            acc[2] = fmaf(Xs[warp * 4 + 2][d], wv, acc[2]);
            acc[3] = fmaf(Xs[warp * 4 + 3][d], wv, acc[3]);
        }
    }

    if (lane < 30) {
        const float bj = bias[lane];
        const float ks = *kappa_scale_p;
        #pragma unroll
        for (int rr = 0; rr < 4; ++rr) {
            int b = b0 + warp * 4 + rr;
            float raw = acc[rr] + bj;
            float val;
            if (lane < 20) {
                // alpha (lane<10) or beta (10<=lane<20): exp(clip(raw,-8,8))
                val = __expf(fminf(fmaxf(raw, -8.f), 8.f));
            } else {
                float dk = __expf(fminf(fmaxf(raw + ks, -8.f), 5.f));
                val = prev_kappa[b * KK + (lane - 20)] + dk;
                out_kappa[b * KK + (lane - 20)] = val;
            }
            g_abk[b * 30 + lane] = val;
        }
    }
}

// Kernel B: per batch row, compute phi[l] (l<seqlen) then w[v] = sum_l phi[l]*oh[b,l,v].
// 4096 blocks x 320 threads. 4 groups of 80 threads (thread<->v), stride-4 over l,
// manual unroll-4 => 16 coalesced 320B row reads in flight per block.
__global__ __launch_bounds__(320) void phi_w_kernel(
    const float* __restrict__ oh, const int* __restrict__ seqlens,
    float* __restrict__ out_w)
{
    __shared__ float s_abk[30];
    __shared__ float s_phi[LL];
    __shared__ float s_red[320];
    const int b   = blockIdx.x;
    const int tid = threadIdx.x;

    if (tid < 30) s_abk[tid] = g_abk[b * 30 + tid];
    __syncthreads();

    const int seqlen = seqlens[b];

    if (tid < LL && tid < seqlen) {
        float u = (float)(tid + 1);
        float s = 0.f;
        #pragma unroll
        for (int k = 0; k < KK; ++k) {
            float al = s_abk[k];
            float be = s_abk[10 + k];
            float ka = s_abk[20 + k];
            float dv = ka - u;
            float e  = fmaxf(-be * dv * dv, -50.f);   // exponent always <= 0
            s = fmaf(al, fast_exp_neg(e), s);
        }
        s_phi[tid] = s;
    }
    __syncthreads();

    const int g = tid / VV;          // group 0..3
    const int v = tid - g * VV;      // 0..79
    const float* row = oh + (size_t)b * (LL * VV) + v;

    float a0 = 0.f, a1 = 0.f, a2 = 0.f, a3 = 0.f;
    int l = g;
    for (; l + 12 < seqlen; l += 16) {
        a0 = fmaf(s_phi[l],      row[(size_t)(l)      * VV], a0);
        a1 = fmaf(s_phi[l + 4],  row[(size_t)(l + 4)  * VV], a1);
        a2 = fmaf(s_phi[l + 8],  row[(size_t)(l + 8)  * VV], a2);
        a3 = fmaf(s_phi[l + 12], row[(size_t)(l + 12) * VV], a3);
    }
    for (; l < seqlen; l += 4)
        a0 = fmaf(s_phi[l], row[(size_t)l * VV], a0);

    s_red[tid] = (a0 + a1) + (a2 + a3);
    __syncthreads();
    if (tid < VV)
        out_w[b * VV + tid] = (s_red[tid] + s_red[tid + 80]) +
                              (s_red[tid + 160] + s_red[tid + 240]);
}

extern "C" void kernel_launch(void* const* d_in, const int* in_sizes, int n_in,
                              void* d_out, int out_size) {
    const float* X          = (const float*)d_in[0];   // [B, D]
    const float* prev_kappa = (const float*)d_in[1];   // [B, K]
    const float* oh         = (const float*)d_in[2];   // [B, L, V]
    const int*   seqlens    = (const int*)  d_in[3];   // [B]
    const float* W          = (const float*)d_in[4];   // [D, 3K]
    const float* bias       = (const float*)d_in[5];   // [3K]
    const float* ks         = (const float*)d_in[6];   // scalar

    float* out       = (float*)d_out;
    float* out_w     = out;              // [B, V] first (reference returns (w, kappa))
    float* out_kappa = out + BQ * VV;    // [B, K] second

    gemm_act_kernel<<<128, 256>>>(X, W, bias, prev_kappa, ks, out_kappa);
    phi_w_kernel<<<BQ, 320>>>(oh, seqlens, out_w);
}

// round 2
// speedup vs baseline: 1.0073x; 1.0073x over previous
#include <cuda_runtime.h>

// Problem constants (from reference): B=4096, D=512, K=10, L=256, V=80
#define BQ 4096
#define DD 512
#define KK 10
#define LL 256
#define VV 80

// Scratch for alpha[0:10], beta[10:20], kappa[20:30] per batch row.
__device__ float g_abk[BQ * 30];

// exp(e) for e in [-50, 0], FMA-pipe only (no MUFU).
// exp(e) = 2^(e*log2e) = 2^i * 2^f, i=floor(t), f in [0,1), deg-6 Taylor (err ~2e-6 rel).
__device__ __forceinline__ float fast_exp_neg(float e) {
    float t = e * 1.44269504088896341f;
    int i = __float2int_rd(t);            // t in [-72.14, 0] -> i in [-73, 0]
    float f = t - (float)i;
    float p = 1.5403530393381610e-4f;
    p = fmaf(p, f, 1.3333558146428443e-3f);
    p = fmaf(p, f, 9.6181291076284772e-3f);
    p = fmaf(p, f, 5.5504108664821580e-2f);
    p = fmaf(p, f, 2.4022650695910071e-1f);
    p = fmaf(p, f, 6.9314718055994531e-1f);
    p = fmaf(p, f, 1.0f);
    return p * __int_as_float((i + 127) << 23);
}

// Kernel A: raw = X@W + b, activations, write kappa to output + abk scratch.
// 128 blocks x 256 threads, each block does 32 batch rows.
// Warp layout: warp w owns rows 4w..4w+3, lane = output column (lanes 30,31 idle at write).
__global__ __launch_bounds__(256) void gemm_act_kernel(
    const float* __restrict__ X, const float* __restrict__ W,
    const float* __restrict__ bias, const float* __restrict__ prev_kappa,
    const float* __restrict__ kappa_scale_p, float* __restrict__ out_kappa)
{
    __shared__ float Xs[32][128];
    __shared__ float Wsh[128 * 30 + 32];   // +32 pad: lanes 30/31 read harmlessly
    const int tid  = threadIdx.x;
    const int warp = tid >> 5;
    const int lane = tid & 31;
    const int b0   = blockIdx.x * 32;

    float acc[4] = {0.f, 0.f, 0.f, 0.f};

    for (int dt = 0; dt < DD; dt += 128) {
        __syncthreads();
        // W slab [dt:dt+128, 0:30] is contiguous in row-major W.
        for (int i = tid; i < 128 * 30; i += 256) Wsh[i] = W[dt * 30 + i];
        for (int i = tid; i < 32 * 128; i += 256) {
            int r = i >> 7, c = i & 127;
            Xs[r][c] = X[(size_t)(b0 + r) * DD + dt + c];
        }
        __syncthreads();
        #pragma unroll 4
        for (int d = 0; d < 128; ++d) {
            float wv = Wsh[d * 30 + lane];
            acc[0] = fmaf(Xs[warp * 4 + 0][d], wv, acc[0]);
            acc[1] = fmaf(Xs[warp * 4 + 1][d], wv, acc[1]);
            acc[2] = fmaf(Xs[warp * 4 + 2][d], wv, acc[2]);
            acc[3] = fmaf(Xs[warp * 4 + 3][d], wv, acc[3]);
        }
    }

    if (lane < 30) {
        const float bj = bias[lane];
        const float ks = *kappa_scale_p;
        #pragma unroll
        for (int rr = 0; rr < 4; ++rr) {
            int b = b0 + warp * 4 + rr;
            float raw = acc[rr] + bj;
            float val;
            if (lane < 20) {
                // alpha (lane<10) or beta (10<=lane<20): exp(clip(raw,-8,8))
                val = __expf(fminf(fmaxf(raw, -8.f), 8.f));
            } else {
                float dk = __expf(fminf(fmaxf(raw + ks, -8.f), 5.f));
                val = prev_kappa[b * KK + (lane - 20)] + dk;
                out_kappa[b * KK + (lane - 20)] = val;
            }
            g_abk[b * 30 + lane] = val;
        }
    }
}

// Kernel B: per batch row, compute phi[l] (l<seqlen) then w[v] = sum_l phi[l]*oh[b,l,v].
// 4096 blocks x 320 threads. 4 groups of 80 threads (thread<->v), stride-4 over l,
// manual unroll-4 => 16 coalesced 320B row reads in flight per block.
__global__ __launch_bounds__(320) void phi_w_kernel(
    const float* __restrict__ oh, const int* __restrict__ seqlens,
    float* __restrict__ out_w)
{
    __shared__ float s_abk[30];
    __shared__ float s_phi[LL];
    __shared__ float s_red[320];
    const int b   = blockIdx.x;
    const int tid = threadIdx.x;

    if (tid < 30) s_abk[tid] = g_abk[b * 30 + tid];
    __syncthreads();

    const int seqlen = seqlens[b];

    if (tid < LL && tid < seqlen) {
        float u = (float)(tid + 1);
        float s = 0.f;
        #pragma unroll
        for (int k = 0; k < KK; ++k) {
            float al = s_abk[k];
            float be = s_abk[10 + k];
            float ka = s_abk[20 + k];
            float dv = ka - u;
            float e  = fmaxf(-be * dv * dv, -50.f);   // exponent always <= 0
            s = fmaf(al, fast_exp_neg(e), s);
        }
        s_phi[tid] = s;
    }
    __syncthreads();

    const int g = tid / VV;          // group 0..3
    const int v = tid - g * VV;      // 0..79
    const float* row = oh + (size_t)b * (LL * VV) + v;

    float a0 = 0.f, a1 = 0.f, a2 = 0.f, a3 = 0.f;
    int l = g;
    for (; l + 12 < seqlen; l += 16) {
        a0 = fmaf(s_phi[l],      row[(size_t)(l)      * VV], a0);
        a1 = fmaf(s_phi[l + 4],  row[(size_t)(l + 4)  * VV], a1);
        a2 = fmaf(s_phi[l + 8],  row[(size_t)(l + 8)  * VV], a2);
        a3 = fmaf(s_phi[l + 12], row[(size_t)(l + 12) * VV], a3);
    }
    for (; l < seqlen; l += 4)
        a0 = fmaf(s_phi[l], row[(size_t)l * VV], a0);

    s_red[tid] = (a0 + a1) + (a2 + a3);
    __syncthreads();
    if (tid < VV)
        out_w[b * VV + tid] = (s_red[tid] + s_red[tid + 80]) +
                              (s_red[tid + 160] + s_red[tid + 240]);
}

extern "C" void kernel_launch(void* const* d_in, const int* in_sizes, int n_in,
                              void* d_out, int out_size) {
    const float* X          = (const float*)d_in[0];   // [B, D]
    const float* prev_kappa = (const float*)d_in[1];   // [B, K]
    const float* oh         = (const float*)d_in[2];   // [B, L, V]
    const int*   seqlens    = (const int*)  d_in[3];   // [B]
    const float* W          = (const float*)d_in[4];   // [D, 3K]
    const float* bias       = (const float*)d_in[5];   // [3K]
    const float* ks         = (const float*)d_in[6];   // scalar

    float* out       = (float*)d_out;
    float* out_w     = out;              // [B, V] first (reference returns (w, kappa))
    float* out_kappa = out + BQ * VV;    // [B, K] second

    gemm_act_kernel<<<128, 256>>>(X, W, bias, prev_kappa, ks, out_kappa);
    phi_w_kernel<<<BQ, 320>>>(oh, seqlens, out_w);
}